// round 15
// baseline (speedup 1.0000x reference)
#include <cuda_runtime.h>
#include <cuda_fp16.h>
#include <math.h>
#include <stdint.h>

#define BB 4
#define CC 64
#define NN 4096
#define RR 4
#define EPSF 1e-6f
#define FSCALE 0.18033688011112042f   // 0.125 * log2(e), folded into Q

typedef unsigned long long u64;

// ---------------- helpers ----------------
__device__ __forceinline__ uint32_t smem_u32(const void* p) {
    uint32_t a;
    asm("{ .reg .u64 t; cvta.to.shared.u64 t, %1; cvt.u32.u64 %0, t; }" : "=r"(a) : "l"(p));
    return a;
}
#define SWZ(off) ((off) ^ (((off) >> 3) & 0x70))   // SW128-style row swizzle

__device__ __forceinline__ void ldmx4(uint32_t* r, uint32_t addr) {
    asm volatile("ldmatrix.sync.aligned.m8n8.x4.shared.b16 {%0,%1,%2,%3}, [%4];"
        : "=r"(r[0]), "=r"(r[1]), "=r"(r[2]), "=r"(r[3]) : "r"(addr));
}
__device__ __forceinline__ void mma16816(float* d, const uint32_t* a,
                                         uint32_t b0, uint32_t b1) {
    asm volatile("mma.sync.aligned.m16n8k16.row.col.f32.f16.f16.f32 "
        "{%0,%1,%2,%3}, {%4,%5,%6,%7}, {%8,%9}, {%0,%1,%2,%3};"
        : "+f"(d[0]), "+f"(d[1]), "+f"(d[2]), "+f"(d[3])
        : "r"(a[0]), "r"(a[1]), "r"(a[2]), "r"(a[3]), "r"(b0), "r"(b1));
}
__device__ __forceinline__ uint32_t packh2(float lo, float hi) {  // lower=lo, upper=hi
    uint32_t r; asm("cvt.rn.f16x2.f32 %0, %1, %2;" : "=r"(r) : "f"(hi), "f"(lo)); return r;
}
#define CP_A16(dst, src) \
    asm volatile("cp.async.cg.shared.global [%0], [%1], 16;" :: "r"(dst), "l"(src) : "memory")
#define CP_COMMIT() asm volatile("cp.async.commit_group;" ::: "memory")
#define CP_WAIT(n)  asm volatile("cp.async.wait_group %0;" :: "n"(n) : "memory")

// ---- packed f32x2 ----
__device__ __forceinline__ u64 pk2f(float lo, float hi) {
    u64 r; asm("mov.b64 %0, {%1,%2};" : "=l"(r) : "f"(lo), "f"(hi)); return r;
}
__device__ __forceinline__ void upk2f(u64 v, float& lo, float& hi) {
    asm("mov.b64 {%0,%1}, %2;" : "=f"(lo), "=f"(hi) : "l"(v));
}
__device__ __forceinline__ u64 add2(u64 a, u64 b) {
    u64 d; asm("add.rn.f32x2 %0, %1, %2;" : "=l"(d) : "l"(a), "l"(b)); return d;
}
__device__ __forceinline__ u64 ffma2(u64 a, u64 b, u64 c) {
    u64 d; asm("fma.rn.f32x2 %0, %1, %2, %3;" : "=l"(d) : "l"(a), "l"(b), "l"(c)); return d;
}
// MUFU exp2 — 1 issue slot per exp
__device__ __forceinline__ float ex2f(float x) {
    float r; asm("ex2.approx.f32 %0, %1;" : "=f"(r) : "f"(x)); return r;
}

// scalar FMA-pipe exp (sigmoids, outside hot loop)
__device__ __forceinline__ float fexp2s(float x) {
    const float MAGIC = 12582912.0f;
    x = fmaxf(x, -80.0f);
    float nf = x + MAGIC;
    float f  = x - (nf - MAGIC);
    float p = 1.3333558146e-3f;
    p = fmaf(p, f, 9.6181298421e-3f);
    p = fmaf(p, f, 5.5504108665e-2f);
    p = fmaf(p, f, 2.4022650696e-1f);
    p = fmaf(p, f, 6.9314718056e-1f);
    p = fmaf(p, f, 1.0f);
    int r = __float_as_int(p) + (__float_as_int(nf) << 23);
    return __int_as_float(r);
}
__device__ __forceinline__ float fexp(float x) { return fexp2s(x * 1.4426950408889634f); }

// ---------------- scratch (device globals) ----------------
__device__ float g_stat[BB][CC][6];
__device__ float g_se[BB][CC];
__device__ float g_W[5][BB][CC][CC];
__device__ float g_bias[5][BB][CC];
__device__ __half g_q[2][BB][NN][CC];    // Q fp16, per branch, [n][c], scaled by FSCALE
__device__ __half g_k[2][BB][NN][CC];    // K fp16, [n][c]
__device__ __half g_v[BB][CC][NN];       // V fp16, [c][n]
__device__ float g_h[2][BB][CC][NN];     // attention outputs

// ================= kernel 1: per-(b,c) sums over HW =================
__global__ void k_stats(const float* __restrict__ x1, const float* __restrict__ x2) {
    int bc = blockIdx.x;
    const float* p1 = x1 + (size_t)bc * NN;
    const float* p2 = x2 + (size_t)bc * NN;
    float s1=0.f,q1=0.f,s2=0.f,q2=0.f,sx=0.f,qx=0.f;
    for (int i = threadIdx.x; i < NN; i += 256) {
        float a = p1[i], b_ = p2[i], s = a + b_;
        s1 += a; q1 += a*a; s2 += b_; q2 += b_*b_; sx += s; qx += s*s;
    }
    __shared__ float red[6][256];
    red[0][threadIdx.x]=s1; red[1][threadIdx.x]=q1; red[2][threadIdx.x]=s2;
    red[3][threadIdx.x]=q2; red[4][threadIdx.x]=sx; red[5][threadIdx.x]=qx;
    __syncthreads();
    for (int off=128; off>=1; off>>=1) {
        if (threadIdx.x < (unsigned)off) {
            #pragma unroll
            for (int k=0;k<6;k++) red[k][threadIdx.x] += red[k][threadIdx.x+off];
        }
        __syncthreads();
    }
    if (threadIdx.x < 6) g_stat[bc/CC][bc%CC][threadIdx.x] = red[threadIdx.x][0];
}

// ==== kernel 2: SE MLP + GroupNorm fold (320 thr: 5 p-folds in parallel) ====
__global__ void __launch_bounds__(320) k_prep(
                       const float* __restrict__ se_w1, const float* __restrict__ se_w2,
                       const float* __restrict__ gamma, const float* __restrict__ beta,
                       const float* __restrict__ wq, const float* __restrict__ bq,
                       const float* __restrict__ wk, const float* __restrict__ bk,
                       const float* __restrict__ wv, const float* __restrict__ bv) {
    int b = blockIdx.x;
    int tid = threadIdx.x;
    __shared__ float sy[CC], sh[RR], sA[3][CC], sBc[3][CC];
    if (tid < CC) {
        int c = tid;
        float st[6], stp[6];
        #pragma unroll
        for (int k=0;k<6;k++) st[k] = g_stat[b][c][k];
        int cp = c ^ 1;
        #pragma unroll
        for (int k=0;k<6;k++) stp[k] = g_stat[b][cp][k];
        sy[c] = st[4] * (1.0f/NN);
        const float inv = 1.0f/(2.0f*NN);
        float ga = gamma[c], be = beta[c];
        #pragma unroll
        for (int t=0;t<3;t++) {
            float mean = (st[2*t]+stp[2*t])*inv;
            float var  = (st[2*t+1]+stp[2*t+1])*inv - mean*mean;
            float rs = rsqrtf(var + EPSF);
            float A = rs*ga;
            sA[t][c] = A;
            sBc[t][c] = be - mean*A;
        }
    }
    __syncthreads();
    if (tid < RR) {
        float h = 0.f;
        for (int ci=0; ci<CC; ci++) h += se_w1[tid*CC+ci]*sy[ci];
        sh[tid] = fmaxf(h, 0.f);
    }
    __syncthreads();
    if (tid < CC) {
        float z = 0.f;
        #pragma unroll
        for (int r=0;r<RR;r++) z += se_w2[tid*RR+r]*sh[r];
        g_se[b][tid] = 1.f/(1.f+fexp(-z));
    }
    // parallel fold: p = tid/64, c = tid%64
    {
        int p = tid >> 6, c = tid & 63;
        const float* w  = (p==0||p==2)? wq : (p==1||p==3)? wk : wv;
        const float* bb = (p==0||p==2)? bq : (p==1||p==3)? bk : bv;
        int t = (p<2)?0 : (p<4)?1 : 2;
        float acc = bb[c];
        for (int ci=0; ci<CC; ci++) {
            float wvl = w[c*CC+ci];
            acc += wvl * sBc[t][ci];
            g_W[p][b][ci][c] = wvl * sA[t][ci];
        }
        g_bias[p][b][c] = acc;
    }
}

// ====== kernel 3: fused projections — load x tile once, emit all 5 ======
__global__ void __launch_bounds__(256) k_proj(const float* __restrict__ x1,
                                              const float* __restrict__ x2) {
    int nt = blockIdx.x, b = blockIdx.y;
    int n0 = nt * 64;
    __shared__ float xs1[CC][64], xs2[CC][64], Wt[CC][CC];
    int tid = threadIdx.x;
    const float* s1 = x1 + (size_t)b*CC*NN + n0;
    const float* s2 = x2 + (size_t)b*CC*NN + n0;
    for (int idx = tid; idx < CC*64; idx += 256) {
        int ci = idx >> 6, n = idx & 63;
        xs1[ci][n] = s1[(size_t)ci*NN + n];
        xs2[ci][n] = s2[(size_t)ci*NN + n];
    }
    int cg = tid >> 4;
    int ng = tid & 15;
    for (int p = 0; p < 5; p++) {
        __syncthreads();                       // Wt reuse / xs1 update ordering
        if (p == 4) {
            for (int idx = tid; idx < CC*64; idx += 256)
                (&xs1[0][0])[idx] += (&xs2[0][0])[idx];
        }
        for (int idx = tid; idx < CC*CC; idx += 256)
            (&Wt[0][0])[idx] = (&g_W[p][b][0][0])[idx];
        __syncthreads();
        float (*xs)[64] = (p < 2) ? xs1 : (p < 4) ? xs2 : xs1;
        u64 acc2[4][2];
        #pragma unroll
        for (int i=0;i<4;i++) {
            float bv_ = g_bias[p][b][4*cg+i];
            acc2[i][0] = pk2f(bv_, bv_); acc2[i][1] = pk2f(bv_, bv_);
        }
        for (int ci=0; ci<CC; ci++) {
            float4 w4 = *(const float4*)&Wt[ci][4*cg];
            float4 x4 = *(const float4*)&xs[ci][4*ng];
            u64 x01 = pk2f(x4.x, x4.y), x23 = pk2f(x4.z, x4.w);
            float wa[4]={w4.x,w4.y,w4.z,w4.w};
            #pragma unroll
            for (int i=0;i<4;i++) {
                u64 wd = pk2f(wa[i], wa[i]);
                acc2[i][0] = ffma2(wd, x01, acc2[i][0]);
                acc2[i][1] = ffma2(wd, x23, acc2[i][1]);
            }
        }
        float acc[4][4];
        #pragma unroll
        for (int i=0;i<4;i++) {
            upk2f(acc2[i][0], acc[i][0], acc[i][1]);
            upk2f(acc2[i][1], acc[i][2], acc[i][3]);
        }
        if (p == 0 || p == 2) {
            int br = p >> 1;
            #pragma unroll
            for (int j=0;j<4;j++) {
                int n = n0 + 4*ng + j;
                uint32_t h01 = packh2(acc[0][j]*FSCALE, acc[1][j]*FSCALE);
                uint32_t h23 = packh2(acc[2][j]*FSCALE, acc[3][j]*FSCALE);
                *(uint2*)&g_q[br][b][n][4*cg] = make_uint2(h01, h23);
            }
        } else if (p == 1 || p == 3) {
            int br = p >> 1;
            #pragma unroll
            for (int j=0;j<4;j++) {
                int n = n0 + 4*ng + j;
                uint32_t h01 = packh2(acc[0][j], acc[1][j]);
                uint32_t h23 = packh2(acc[2][j], acc[3][j]);
                *(uint2*)&g_k[br][b][n][4*cg] = make_uint2(h01, h23);
            }
        } else {
            #pragma unroll
            for (int i=0;i<4;i++) {
                int c = 4*cg + i;
                uint32_t h01 = packh2(acc[i][0], acc[i][1]);
                uint32_t h23 = packh2(acc[i][2], acc[i][3]);
                *(uint2*)&g_v[b][c][n0 + 4*ng] = make_uint2(h01, h23);
            }
        }
    }
}

// ============== kernel 4: mma.sync flash attention, M=32 per warp ==============
// 64 thr / 2 warps; warp w owns q rows [32w, 32w+32) as two 16-row groups sharing
// K fragments. Phase order S -> sm-A -> PV-A -> sm-B -> PV-B so the S-results
// stall also drains prior PV (clears the vf WAR for the next iteration) and PV-A
// feeds the tensor pipe during softmax-B. 3-stage cp.async ring, MUFU softmax.
#define STG 16384
__global__ void __launch_bounds__(64, 4) k_attn() {
    __shared__ __align__(128) char smem[49152];   // 3 x (K 8KB | V 8KB)
    uint32_t sb = smem_u32(smem);
    int tid = threadIdx.x, l = tid & 31, w = tid >> 5;
    int qt = blockIdx.x;
    int bbi = blockIdx.y; int b = bbi >> 1, br = bbi & 1;

    const __half* Q = &g_q[br][b][qt*64][0];
    const __half* K = &g_k[br][b][0][0];
    const __half* V = &g_v[b][0][0];

    // ---- Q tile (64 rows) into stage0, ldmatrix to regs (2 groups/warp) ----
    for (int u = tid; u < 512; u += 64) {
        int r = u >> 3, q = u & 7;
        *(uint4*)(smem + SWZ(r*128 + q*16)) = ((const uint4*)(Q + r*64))[q];
    }
    __syncthreads();
    uint32_t qA[4][4], qB[4][4];
    {
        int arowA = 32*w + ((l>>3)&1)*8 + (l&7);
        int acolh = ((l>>4)&1)*16;
        #pragma unroll
        for (int ks = 0; ks < 4; ks++) {
            ldmx4(qA[ks], sb + SWZ(arowA*128 + ks*32 + acolh));
            ldmx4(qB[ks], sb + SWZ((arowA+16)*128 + ks*32 + acolh));
        }
    }
    __syncthreads();

    // ---- per-thread hoisted cp.async offsets (64 thr -> 8 rows each) ----
    uint32_t soff[8]; int gK[8]; size_t gV[8];
    {
        int rt = tid >> 3, q = tid & 7;
        #pragma unroll
        for (int i = 0; i < 8; i++) {
            int r = rt + 8*i;
            soff[i] = SWZ(r*128 + q*16);
            gK[i] = r*64 + q*8;
            gV[i] = (size_t)r*NN + q*8;
        }
    }
    // ---- preload tiles 0 and 1 ----
    #pragma unroll
    for (int pre = 0; pre < 2; pre++) {
        uint32_t base = sb + pre*STG;
        const __half* kg = K + (size_t)pre*64*CC;
        const __half* vg = V + pre*64;
        #pragma unroll
        for (int i = 0; i < 8; i++) {
            CP_A16(base + soff[i],        kg + gK[i]);
            CP_A16(base + 8192 + soff[i], vg + gV[i]);
        }
        CP_COMMIT();
    }

    float oA[8][4], oB[8][4];
    #pragma unroll
    for (int u=0;u<8;u++) {
        oA[u][0]=0.f; oA[u][1]=0.f; oA[u][2]=0.f; oA[u][3]=0.f;
        oB[u][0]=0.f; oB[u][1]=0.f; oB[u][2]=0.f; oB[u][3]=0.f;
    }
    u64 lsA0 = 0, lsA1 = 0, lsB0 = 0, lsB1 = 0;

    int brow = ((l>>4)&1)*8 + (l&7);
    int bcolh = ((l>>3)&1)*16;

    int stage = 0;
    for (int kt = 0; kt < 64; kt++) {
        if (kt == 63) { CP_WAIT(0); } else { CP_WAIT(1); }
        __syncthreads();               // stage kt ready; both warps done with kt-1
        uint32_t base = sb + stage*STG;
        if (kt < 62) {                 // prefetch kt+2 into stage last read at kt-1
            int ps = stage + 2; if (ps >= 3) ps -= 3;
            uint32_t pbase = sb + ps*STG;
            const __half* kg = K + (size_t)(kt+2)*64*CC;
            const __half* vg = V + (kt+2)*64;
            #pragma unroll
            for (int i = 0; i < 8; i++) {
                CP_A16(pbase + soff[i],        kg + gK[i]);
                CP_A16(pbase + 8192 + soff[i], vg + gV[i]);
            }
            CP_COMMIT();
        }
        // ---- S = Q*K for both row groups, sharing K fragments ----
        float scA[8][4], scB[8][4];
        #pragma unroll
        for (int u=0;u<8;u++) {
            scA[u][0]=0.f; scA[u][1]=0.f; scA[u][2]=0.f; scA[u][3]=0.f;
            scB[u][0]=0.f; scB[u][1]=0.f; scB[u][2]=0.f; scB[u][3]=0.f;
        }
        #pragma unroll
        for (int ks = 0; ks < 4; ks++) {
            uint32_t kf[4][4];
            #pragma unroll
            for (int up = 0; up < 4; up++)
                ldmx4(kf[up], base + SWZ((16*up + brow)*128 + ks*32 + bcolh));
            #pragma unroll
            for (int up = 0; up < 4; up++) {
                mma16816(scA[2*up],   qA[ks], kf[up][0], kf[up][1]);
                mma16816(scA[2*up+1], qA[ks], kf[up][2], kf[up][3]);
                mma16816(scB[2*up],   qB[ks], kf[up][0], kf[up][1]);
                mma16816(scB[2*up+1], qB[ks], kf[up][2], kf[up][3]);
            }
        }
        // ---- softmax-A (MUFU) then PV-A ----
        {
            uint32_t ph[8][2];
            #pragma unroll
            for (int u = 0; u < 8; u++) {
                float a0 = ex2f(scA[u][0]), a1 = ex2f(scA[u][1]);
                float a2 = ex2f(scA[u][2]), a3 = ex2f(scA[u][3]);
                lsA0 = add2(lsA0, pk2f(a0, a1));
                lsA1 = add2(lsA1, pk2f(a2, a3));
                ph[u][0] = packh2(a0, a1); ph[u][1] = packh2(a2, a3);
            }
            #pragma unroll
            for (int t = 0; t < 4; t++) {
                uint32_t aA[4] = { ph[2*t][0], ph[2*t][1], ph[2*t+1][0], ph[2*t+1][1] };
                uint32_t vf[4][4];
                #pragma unroll
                for (int up = 0; up < 4; up++)
                    ldmx4(vf[up], base + 8192 + SWZ((16*up + brow)*128 + t*32 + bcolh));
                #pragma unroll
                for (int up = 0; up < 4; up++) {
                    mma16816(oA[2*up],   aA, vf[up][0], vf[up][1]);
                    mma16816(oA[2*up+1], aA, vf[up][2], vf[up][3]);
                }
            }
        }
        // ---- softmax-B then PV-B ----
        {
            uint32_t ph[8][2];
            #pragma unroll
            for (int u = 0; u < 8; u++) {
                float b0 = ex2f(scB[u][0]), b1 = ex2f(scB[u][1]);
                float b2 = ex2f(scB[u][2]), b3 = ex2f(scB[u][3]);
                lsB0 = add2(lsB0, pk2f(b0, b1));
                lsB1 = add2(lsB1, pk2f(b2, b3));
                ph[u][0] = packh2(b0, b1); ph[u][1] = packh2(b2, b3);
            }
            #pragma unroll
            for (int t = 0; t < 4; t++) {
                uint32_t aB[4] = { ph[2*t][0], ph[2*t][1], ph[2*t+1][0], ph[2*t+1][1] };
                uint32_t vf[4][4];
                #pragma unroll
                for (int up = 0; up < 4; up++)
                    ldmx4(vf[up], base + 8192 + SWZ((16*up + brow)*128 + t*32 + bcolh));
                #pragma unroll
                for (int up = 0; up < 4; up++) {
                    mma16816(oB[2*up],   aB, vf[up][0], vf[up][1]);
                    mma16816(oB[2*up+1], aB, vf[up][2], vf[up][3]);
                }
            }
        }
        if (++stage == 3) stage = 0;
    }
    // ---- row sums across the quad, normalize ----
    {
        float s0, s1, t0, t1;
        upk2f(lsA0, s0, t0); s0 += t0;
        upk2f(lsA1, s1, t1); s1 += t1;
        s0 += __shfl_xor_sync(0xffffffffu, s0, 1);
        s0 += __shfl_xor_sync(0xffffffffu, s0, 2);
        s1 += __shfl_xor_sync(0xffffffffu, s1, 1);
        s1 += __shfl_xor_sync(0xffffffffu, s1, 2);
        float r0 = 1.0f/s0, r1 = 1.0f/s1;
        #pragma unroll
        for (int u=0;u<8;u++) { oA[u][0]*=r0; oA[u][1]*=r0; oA[u][2]*=r1; oA[u][3]*=r1; }
        upk2f(lsB0, s0, t0); s0 += t0;
        upk2f(lsB1, s1, t1); s1 += t1;
        s0 += __shfl_xor_sync(0xffffffffu, s0, 1);
        s0 += __shfl_xor_sync(0xffffffffu, s0, 2);
        s1 += __shfl_xor_sync(0xffffffffu, s1, 1);
        s1 += __shfl_xor_sync(0xffffffffu, s1, 2);
        r0 = 1.0f/s0; r1 = 1.0f/s1;
        #pragma unroll
        for (int u=0;u<8;u++) { oB[u][0]*=r0; oB[u][1]*=r0; oB[u][2]*=r1; oB[u][3]*=r1; }
    }
    // ---- transpose both groups via smem, write g_h ----
    __syncthreads();   // ring drained (CP_WAIT(0) done); smem reusable
    float* Wp = (float*)smem + w * 1088;         // 64 rows x stride 17 per warp
    float* H = &g_h[br][b][0][0];
    #pragma unroll
    for (int g = 0; g < 2; g++) {
        float (*og)[4] = g ? oB : oA;
        __syncwarp();
        #pragma unroll
        for (int u = 0; u < 8; u++) {
            int c0 = 8*u + 2*(l&3);
            int r  = l >> 2;
            Wp[c0*17 + r]       = og[u][0];
            Wp[(c0+1)*17 + r]   = og[u][1];
            Wp[c0*17 + r + 8]   = og[u][2];
            Wp[(c0+1)*17 + r+8] = og[u][3];
        }
        __syncwarp();
        int n0 = qt*64 + 32*w + 16*g;
        #pragma unroll
        for (int rep = 0; rep < 2; rep++) {
            int cc = 2*l + rep;
            #pragma unroll
            for (int k4 = 0; k4 < 4; k4++) {
                float4 v = make_float4(Wp[cc*17+4*k4], Wp[cc*17+4*k4+1],
                                       Wp[cc*17+4*k4+2], Wp[cc*17+4*k4+3]);
                *(float4*)&H[(size_t)cc*NN + n0 + 4*k4] = v;
            }
        }
    }
}

// ================= kernel 5: final combine =================
__global__ void k_final(const float* __restrict__ x1, const float* __restrict__ x2,
                        float* __restrict__ out) {
    int idx4 = blockIdx.x*256 + threadIdx.x;
    if (idx4 >= BB*CC*NN/4) return;
    int idx = idx4 * 4;
    int bc = idx >> 12;
    int b = bc >> 6, c = bc & 63;
    float se = g_se[b][c];
    float4 a1 = *(const float4*)&x1[idx];
    float4 a2 = *(const float4*)&x2[idx];
    float4 h1 = *(const float4*)(&g_h[0][0][0][0] + idx);
    float4 h2 = *(const float4*)(&g_h[1][0][0][0] + idx);
    float xs[4] = {a1.x+a2.x, a1.y+a2.y, a1.z+a2.z, a1.w+a2.w};
    float h1a[4]={h1.x,h1.y,h1.z,h1.w};
    float h2a[4]={h2.x,h2.y,h2.z,h2.w};
    float oa[4];
    #pragma unroll
    for (int k=0;k<4;k++) {
        float ww = 1.f/(1.f+fexp(-xs[k]*se));
        oa[k] = 2.f*h1a[k]*ww + 2.f*h2a[k]*(1.f-ww);
    }
    *(float4*)&out[idx] = make_float4(oa[0],oa[1],oa[2],oa[3]);
}

// ================= launcher =================
extern "C" void kernel_launch(void* const* d_in, const int* in_sizes, int n_in,
                              void* d_out, int out_size) {
    const float* x1    = (const float*)d_in[0];
    const float* x2    = (const float*)d_in[1];
    const float* se_w1 = (const float*)d_in[2];
    const float* se_w2 = (const float*)d_in[3];
    const float* gam   = (const float*)d_in[4];
    const float* bet   = (const float*)d_in[5];
    const float* wq    = (const float*)d_in[6];
    const float* bq    = (const float*)d_in[7];
    const float* wk    = (const float*)d_in[8];
    const float* bk    = (const float*)d_in[9];
    const float* wv    = (const float*)d_in[10];
    const float* bv    = (const float*)d_in[11];
    float* out = (float*)d_out;

    k_stats<<<BB*CC, 256>>>(x1, x2);
    k_prep<<<BB, 320>>>(se_w1, se_w2, gam, bet, wq, bq, wk, bk, wv, bv);
    k_proj<<<dim3(64, BB), 256>>>(x1, x2);
    k_attn<<<dim3(64, 8), 64>>>();
    k_final<<<(BB*CC*NN/4 + 255)/256, 256>>>(x1, x2, out);
}